// round 16
// baseline (speedup 1.0000x reference)
#include <cuda_runtime.h>
#include <cuda_fp16.h>
#include <cstdint>

#define D 64
#define N_MAX 200000
#define E_MAX 4000000
#define SCAN_T 1024

// ---- scratch (static device globals; zero-initialized at module load) ----
__device__ int     g_deg[N_MAX];       // zeroed at load; re-zeroed by k_final each call
__device__ int     g_off[N_MAX];
__device__ float   g_dinv[N_MAX];
__device__ __align__(16) int g_pr[E_MAX];       // packed (dst<<12)|rank
__device__ __align__(16) int g_src[E_MAX];      // CSR adjacency: src only
__device__ __half2 g_s0[(size_t)N_MAX * 32];    // s0 = dinv ⊙ emb0 (fp16)
__device__ __half2 g_s1[(size_t)N_MAX * 32];    // s1 = dinv ⊙ e1
__device__ __half2 g_s2[(size_t)N_MAX * 32];    // s2 = dinv ⊙ e2
__device__ int          g_bsum[256];
__device__ volatile int g_bflag[256];           // lookback flags; reset by k_final

// ------- degree count + packed rank record (4 edges/thread) + fused out0 copy -------
__global__ void k_count(const int* __restrict__ dst, int E,
                        const float4* __restrict__ emb, float4* __restrict__ o0,
                        int n4) {
    int tid = blockIdx.x * blockDim.x + threadIdx.x;
    int i = tid * 4;
    if (i + 3 < E) {
        int4 d = *reinterpret_cast<const int4*>(dst + i);
        int4 p;
        p.x = (d.x << 12) | atomicAdd(&g_deg[d.x], 1);
        p.y = (d.y << 12) | atomicAdd(&g_deg[d.y], 1);
        p.z = (d.z << 12) | atomicAdd(&g_deg[d.z], 1);
        p.w = (d.w << 12) | atomicAdd(&g_deg[d.w], 1);
        *reinterpret_cast<int4*>(g_pr + i) = p;
    } else {
        for (int k = i; k < E; ++k) {
            int d = dst[k];
            g_pr[k] = (d << 12) | atomicAdd(&g_deg[d], 1);
        }
    }
    // fused: out0 = emb0 (independent streaming work in the atomic shadow)
    int stride = gridDim.x * blockDim.x;
    for (int k = tid; k < n4; k += stride) o0[k] = emb[k];
}

// ------- single-pass exclusive scan (decoupled lookback) + dinv fused -------
__global__ void k_scan(int n, int nb) {
    __shared__ int s[SCAN_T];
    __shared__ int s_excl;
    int t = threadIdx.x;
    int b = blockIdx.x;
    int i = b * SCAN_T + t;
    int v = (i < n) ? g_deg[i] : 0;
    s[t] = v;
    __syncthreads();
    for (int d = 1; d < SCAN_T; d <<= 1) {
        int x = (t >= d) ? s[t - d] : 0;
        __syncthreads();
        s[t] += x;
        __syncthreads();
    }
    if (t == SCAN_T - 1) {
        g_bsum[b] = s[t];
        __threadfence();
        g_bflag[b] = 1;
    }
    int part = 0;
    if (t < b) {
        while (g_bflag[t] == 0) { }
        part = g_bsum[t];
    }
    for (int o = 16; o > 0; o >>= 1) part += __shfl_down_sync(0xffffffffu, part, o);
    __shared__ int wsum[32];
    if ((t & 31) == 0) wsum[t >> 5] = part;
    __syncthreads();
    if (t < 32) {
        int x = (t < (SCAN_T / 32)) ? wsum[t] : 0;
        for (int o = 16; o > 0; o >>= 1) x += __shfl_down_sync(0xffffffffu, x, o);
        if (t == 0) s_excl = x;
    }
    __syncthreads();
    if (i < n) {
        g_off[i]  = s[t] - v + s_excl;
        g_dinv[i] = (v > 0) ? rsqrtf((float)v) : 0.0f;
    }
}

// ------- CSR fill from packed rank (no dst read, no atomic) + fused s0 build -------
__global__ void k_fill(const int* __restrict__ src, int E,
                       const float4* __restrict__ emb, int n4) {
    int tid = blockIdx.x * blockDim.x + threadIdx.x;
    int i = tid * 4;
    if (i + 3 < E) {
        int4 s = *reinterpret_cast<const int4*>(src + i);
        int4 p = *reinterpret_cast<const int4*>(g_pr + i);
        g_src[g_off[p.x >> 12] + (p.x & 4095)] = s.x;
        g_src[g_off[p.y >> 12] + (p.y & 4095)] = s.y;
        g_src[g_off[p.z >> 12] + (p.z & 4095)] = s.z;
        g_src[g_off[p.w >> 12] + (p.w & 4095)] = s.w;
    } else {
        for (int k = i; k < E; ++k) {
            int p = g_pr[k];
            g_src[g_off[p >> 12] + (p & 4095)] = src[k];
        }
    }
    int stride = gridDim.x * blockDim.x;
    for (int k = tid; k < n4; k += stride) {
        float4 v = emb[k];
        float dv = g_dinv[k >> 4];                 // 16 float4 per node row
        g_s0[2 * k]     = __float22half2_rn(make_float2(v.x * dv, v.y * dv));
        g_s0[2 * k + 1] = __float22half2_rn(make_float2(v.z * dv, v.w * dv));
    }
}

// ---------------- gather-sum: warp per node, half-warp per edge ----------------
// Main loop accumulates in fp16 (HADD2 chains, 8 terms/chunk) and flushes to
// fp32 once per 16-edge trip: FP instruction count per edge drops 8 -> ~2.75.
#define HC(u) (*reinterpret_cast<const __half2*>(&(u)))
#define ACC(r) do { \
    float2 _fa = __half22float2(HC((r).x)); \
    float2 _fb = __half22float2(HC((r).y)); \
    ax += _fa.x; ay += _fa.y; az += _fb.x; aw += _fb.y; } while (0)

__device__ __forceinline__ float4 gather_sum2(const uint2* __restrict__ in2,
                                              int lo, int end, int side, int sub) {
    float ax = 0.f, ay = 0.f, az = 0.f, aw = 0.f;
    int j = lo;
    while (j < end && (j & 3)) {
        if ((j & 1) == side) {
            uint2 r = in2[(((size_t)g_src[j]) << 4) + sub];
            ACC(r);
        }
        ++j;
    }
    const int4* __restrict__ s4 = reinterpret_cast<const int4*>(g_src);
    for (; j + 16 <= end; j += 16) {
        int4 a = s4[(j >> 2) + 0];
        int4 b = s4[(j >> 2) + 1];
        int4 c = s4[(j >> 2) + 2];
        int4 d = s4[(j >> 2) + 3];
        int i0 = side ? a.y : a.x;
        int i1 = side ? a.w : a.z;
        int i2 = side ? b.y : b.x;
        int i3 = side ? b.w : b.z;
        int i4 = side ? c.y : c.x;
        int i5 = side ? c.w : c.z;
        int i6 = side ? d.y : d.x;
        int i7 = side ? d.w : d.z;
        uint2 r0 = in2[(((size_t)i0) << 4) + sub];
        uint2 r1 = in2[(((size_t)i1) << 4) + sub];
        uint2 r2 = in2[(((size_t)i2) << 4) + sub];
        uint2 r3 = in2[(((size_t)i3) << 4) + sub];
        uint2 r4 = in2[(((size_t)i4) << 4) + sub];
        uint2 r5 = in2[(((size_t)i5) << 4) + sub];
        uint2 r6 = in2[(((size_t)i6) << 4) + sub];
        uint2 r7 = in2[(((size_t)i7) << 4) + sub];
        // fp16 chunk accumulation: two independent HADD2 chains
        __half2 p = HC(r0.x), q = HC(r0.y);
        p = __hadd2(p, HC(r1.x));  q = __hadd2(q, HC(r1.y));
        p = __hadd2(p, HC(r2.x));  q = __hadd2(q, HC(r2.y));
        p = __hadd2(p, HC(r3.x));  q = __hadd2(q, HC(r3.y));
        p = __hadd2(p, HC(r4.x));  q = __hadd2(q, HC(r4.y));
        p = __hadd2(p, HC(r5.x));  q = __hadd2(q, HC(r5.y));
        p = __hadd2(p, HC(r6.x));  q = __hadd2(q, HC(r6.y));
        p = __hadd2(p, HC(r7.x));  q = __hadd2(q, HC(r7.y));
        float2 fp = __half22float2(p);
        float2 fq = __half22float2(q);
        ax += fp.x; ay += fp.y; az += fq.x; aw += fq.y;   // flush once per trip
    }
    for (; j + 4 <= end; j += 4) {
        int4 a = s4[j >> 2];
        int i0 = side ? a.y : a.x;
        int i1 = side ? a.w : a.z;
        uint2 r0 = in2[(((size_t)i0) << 4) + sub];
        uint2 r1 = in2[(((size_t)i1) << 4) + sub];
        ACC(r0); ACC(r1);
    }
    while (j < end) {
        if ((j & 1) == side) {
            uint2 r = in2[(((size_t)g_src[j]) << 4) + sub];
            ACC(r);
        }
        ++j;
    }
    ax += __shfl_xor_sync(0xffffffffu, ax, 16);
    ay += __shfl_xor_sync(0xffffffffu, ay, 16);
    az += __shfl_xor_sync(0xffffffffu, az, 16);
    aw += __shfl_xor_sync(0xffffffffu, aw, 16);
    return make_float4(ax, ay, az, aw);
}

// layers 0/1: s_out[v] = fp16( dinv[v]^2 * Σ s_in[src] )   [invariant: s = dinv ⊙ e]
__global__ void __launch_bounds__(256) k_prop(const __half2* __restrict__ in,
                                              __half2* __restrict__ out, int n) {
    int warp = (blockIdx.x * blockDim.x + threadIdx.x) >> 5;
    int lane = threadIdx.x & 31;
    if (warp >= n) return;
    int side = lane >> 4, sub = lane & 15;
    int lo = g_off[warp];
    float4 s = gather_sum2(reinterpret_cast<const uint2*>(in),
                           lo, lo + g_deg[warp], side, sub);
    if (side == 0) {
        float dv = g_dinv[warp];
        float d2 = dv * dv;
        __half2 oa = __float22half2_rn(make_float2(s.x * d2, s.y * d2));
        __half2 ob = __float22half2_rn(make_float2(s.z * d2, s.w * d2));
        uint2 o;
        o.x = *reinterpret_cast<unsigned*>(&oa);
        o.y = *reinterpret_cast<unsigned*>(&ob);
        reinterpret_cast<uint2*>(out)[(((size_t)warp) << 4) + sub] = o;
    }
}

// final: out = (emb0 + (s1+s2)*sqrt(deg) + dinv*Σ s2[src]) * 0.25; reset g_deg/g_bflag
__global__ void __launch_bounds__(256) k_final(const float* __restrict__ emb0,
                                               float* __restrict__ outp, int n) {
    int warp = (blockIdx.x * blockDim.x + threadIdx.x) >> 5;
    int lane = threadIdx.x & 31;
    if (blockIdx.x == 0 && threadIdx.x < 256) g_bflag[threadIdx.x] = 0;
    if (warp >= n) return;
    int side = lane >> 4, sub = lane & 15;
    int lo = g_off[warp];
    int dg = g_deg[warp];
    float4 s = gather_sum2(reinterpret_cast<const uint2*>(g_s2),
                           lo, lo + dg, side, sub);

    if (side == 0) {
        float dv = g_dinv[warp];
        float sq = sqrtf((float)dg);               // e_k = s_k * sqrt(deg)
        size_t ro = (((size_t)warp) << 4) + sub;
        float4 e0 = reinterpret_cast<const float4*>(emb0)[ro];
        uint2 r1 = reinterpret_cast<const uint2*>(g_s1)[ro];
        uint2 r2 = reinterpret_cast<const uint2*>(g_s2)[ro];
        float2 a1a = __half22float2(HC(r1.x));
        float2 a1b = __half22float2(HC(r1.y));
        float2 a2a = __half22float2(HC(r2.x));
        float2 a2b = __half22float2(HC(r2.y));
        float4 r;
        r.x = (e0.x + (a1a.x + a2a.x) * sq + s.x * dv) * 0.25f;
        r.y = (e0.y + (a1a.y + a2a.y) * sq + s.y * dv) * 0.25f;
        r.z = (e0.z + (a1b.x + a2b.x) * sq + s.z * dv) * 0.25f;
        r.w = (e0.w + (a1b.y + a2b.y) * sq + s.w * dv) * 0.25f;
        reinterpret_cast<float4*>(outp)[ro] = r;
    }
    if (lane == 0) g_deg[warp] = 0;   // restore invariant for next graph replay
}

extern "C" void kernel_launch(void* const* d_in, const int* in_sizes, int n_in,
                              void* d_out, int out_size) {
    const int*   edges = (const int*)d_in[0];       // int32
    const float* emb   = (const float*)d_in[1];
    int E = in_sizes[0] / 2;
    int N = in_sizes[1] / D;

    const int* src = edges;
    const int* dst = edges + E;

    float* out0 = (float*)d_out;
    float* outp = out0 + (size_t)N * D;

    int tb = 256;
    int nbE4 = ((E + 3) / 4 + tb - 1) / tb;         // 4 edges per thread
    int NB   = (N + SCAN_T - 1) / SCAN_T;           // 196
    int n4   = (N * D) / 4;

    k_count<<<nbE4, tb>>>(dst, E, (const float4*)emb, (float4*)out0, n4); // 0 (+out0)
    k_scan<<<NB, SCAN_T>>>(N, NB);                                        // 1 (scan+dinv)
    k_fill<<<nbE4, tb>>>(src, E, (const float4*)emb, n4);                 // 2 (+s0)

    __half2 *s0p, *s1p, *s2p;
    cudaGetSymbolAddress((void**)&s0p, g_s0);
    cudaGetSymbolAddress((void**)&s1p, g_s1);
    cudaGetSymbolAddress((void**)&s2p, g_s2);

    int pthreads = N * 32;                          // one warp per node
    int pblocks  = (pthreads + tb - 1) / tb;
    k_prop<<<pblocks, tb>>>(s0p, s1p, N);           // 3  <- profiled launch
    k_prop<<<pblocks, tb>>>(s1p, s2p, N);           // 4
    k_final<<<pblocks, tb>>>(emb, outp, N);         // 5
}